// round 10
// baseline (speedup 1.0000x reference)
#include <cuda_runtime.h>
#include <cstdint>

// NativeSparseAttention: S=8192, B=16, E=128, fp32
// Persistent kernel, warp-level tf32 mma.sync (m16n8k8), 256 threads, 1 CTA/SM.
// R9: W fragments register-resident (128 regs); xf cache dropped (P3 reloads x)
//     to stay under the register cap (R8 hit 255 -> spills).

#define S_TOTAL 8192

// strides (floats)
#define SX 136
#define SK 20
#define SV 136
#define SE 136
#define SWS 132   // W staging stride (startup only)

// smem offsets (floats)
#define OFF_X   0                          // 16 x SX        = 2176
#define OFF_K   2176                       // 128 x SK       = 2560
#define OFF_INV 4736                       // 128
#define OFF_V   4864                       // 128 x SV       = 17408
#define OFF_E   22272                      // 128 x SE       = 17408
#define SMEM_FLOATS 39680
#define SMEM_BYTES  (SMEM_FLOATS * 4)      // 158720
// startup W staging: Wk at OFF_V, Wv at OFF_V + 16896 (fits before SMEM end)
#define OFF_SCR OFF_V

__device__ __forceinline__ uint32_t f2t(float f) {
    uint32_t u; asm("cvt.rna.tf32.f32 %0, %1;" : "=r"(u) : "f"(f)); return u;
}
__device__ __forceinline__ float ex2f(float x) {
    float y; asm("ex2.approx.f32 %0, %1;" : "=f"(y) : "f"(x)); return y;
}
__device__ __forceinline__ void mma8(float* d, const uint32_t* a, const uint32_t* b) {
    asm volatile(
        "mma.sync.aligned.m16n8k8.row.col.f32.tf32.tf32.f32 "
        "{%0,%1,%2,%3}, {%4,%5,%6,%7}, {%8,%9}, {%0,%1,%2,%3};"
        : "+f"(d[0]), "+f"(d[1]), "+f"(d[2]), "+f"(d[3])
        : "r"(a[0]), "r"(a[1]), "r"(a[2]), "r"(a[3]), "r"(b[0]), "r"(b[1]));
}

__global__ __launch_bounds__(256, 1)
void nsa_mma(const float* __restrict__ x,
             const float* __restrict__ Wk,
             const float* __restrict__ bk,
             const float* __restrict__ Wv,
             const float* __restrict__ bv,
             float* __restrict__ out) {
    extern __shared__ float sm[];
    uint32_t* smu = reinterpret_cast<uint32_t*>(sm);

    const int t = threadIdx.x;
    const int wid = t >> 5;
    const int lid = t & 31;
    const int qr = lid >> 2;    // groupID 0..7
    const int qc = lid & 3;     // threadID-in-group 0..3
    const int ebk = wid * 16;   // warp's e-block base

    // ---- startup: stage W to scratch smem, extract per-warp A-fragments ----
    #pragma unroll
    for (int i = 0; i < 16; i++) {
        const int l = t + 256 * i;          // float4 index over 128x128
        const int r = l >> 5, c = (l & 31) * 4;
        float4 a = reinterpret_cast<const float4*>(Wk)[l];
        uint4 pa = { f2t(a.x), f2t(a.y), f2t(a.z), f2t(a.w) };
        *reinterpret_cast<uint4*>(&smu[OFF_SCR + r * SWS + c]) = pa;
        float4 b = reinterpret_cast<const float4*>(Wv)[l];
        uint4 pb = { f2t(b.x), f2t(b.y), f2t(b.z), f2t(b.w) };
        *reinterpret_cast<uint4*>(&smu[OFF_SCR + 16896 + r * SWS + c]) = pb;
    }
    __syncthreads();

    uint32_t wkf[16][4], wvf[16][4];
    #pragma unroll
    for (int kk = 0; kk < 16; kk++) {
        const int jb = kk * 8;
        wkf[kk][0] = smu[OFF_SCR + (ebk + qr) * SWS + jb + qc];
        wkf[kk][1] = smu[OFF_SCR + (ebk + qr + 8) * SWS + jb + qc];
        wkf[kk][2] = smu[OFF_SCR + (ebk + qr) * SWS + jb + qc + 4];
        wkf[kk][3] = smu[OFF_SCR + (ebk + qr + 8) * SWS + jb + qc + 4];
        wvf[kk][0] = smu[OFF_SCR + 16896 + (ebk + qr) * SWS + jb + qc];
        wvf[kk][1] = smu[OFF_SCR + 16896 + (ebk + qr + 8) * SWS + jb + qc];
        wvf[kk][2] = smu[OFF_SCR + 16896 + (ebk + qr) * SWS + jb + qc + 4];
        wvf[kk][3] = smu[OFF_SCR + 16896 + (ebk + qr + 8) * SWS + jb + qc + 4];
    }
    const float bk0 = __ldg(bk + ebk + qr), bk1 = __ldg(bk + ebk + qr + 8);
    const float bv0 = __ldg(bv + ebk + qr), bv1 = __ldg(bv + ebk + qr + 8);
    const float C2 = 0.015939678942f;       // log2(e)/sqrt(8192)
    __syncthreads();                        // scratch reads done before v reuse

    int s = blockIdx.x;
    float4 xr0, xr1;
    if (s < S_TOTAL) {
        const float4* xg = reinterpret_cast<const float4*>(x + (size_t)s * 2048);
        xr0 = xg[t]; xr1 = xg[t + 256];
    }

    while (s < S_TOTAL) {
        // ---- stage x (tf32) into [b][j] stride SX ----
        {
            const int b0i = t >> 5,         c0 = (t & 31) * 4;
            const int b1i = (t + 256) >> 5, c1 = ((t + 256) & 31) * 4;
            uint4 h;
            h.x = f2t(xr0.x); h.y = f2t(xr0.y); h.z = f2t(xr0.z); h.w = f2t(xr0.w);
            *reinterpret_cast<uint4*>(&smu[OFF_X + b0i * SX + c0]) = h;
            h.x = f2t(xr1.x); h.y = f2t(xr1.y); h.z = f2t(xr1.z); h.w = f2t(xr1.w);
            *reinterpret_cast<uint4*>(&smu[OFF_X + b1i * SX + c1]) = h;
        }
        __syncthreads();

        // ---- prefetch next x into regs ----
        const int snext = s + gridDim.x;
        if (snext < S_TOTAL) {
            const float4* xg = reinterpret_cast<const float4*>(x + (size_t)snext * 2048);
            xr0 = xg[t]; xr1 = xg[t + 256];
        }

        // ======== phase 1: kT = Wk@xT, vT = Wv@xT  (M=e16, N=b16, K=128) ========
        float kD[2][4] = {{0,0,0,0},{0,0,0,0}};
        float vD[2][4] = {{0,0,0,0},{0,0,0,0}};
        #pragma unroll
        for (int kk = 0; kk < 16; kk++) {
            const int jb = kk * 8;
            uint32_t xb[4];
            xb[0] = smu[OFF_X + qr * SX + jb + qc];
            xb[1] = smu[OFF_X + qr * SX + jb + qc + 4];
            xb[2] = smu[OFF_X + (qr + 8) * SX + jb + qc];
            xb[3] = smu[OFF_X + (qr + 8) * SX + jb + qc + 4];
            mma8(kD[0], wkf[kk], &xb[0]); mma8(kD[1], wkf[kk], &xb[2]);
            mma8(vD[0], wvf[kk], &xb[0]); mma8(vD[1], wvf[kk], &xb[2]);
        }
        // store k as [e][b] (stride SK), v as [b][f] (stride SV), +bias, tf32
        #pragma unroll
        for (int nt = 0; nt < 2; nt++) {
            const int bcol = nt * 8 + 2 * qc;
            smu[OFF_K + (ebk + qr) * SK + bcol]         = f2t(kD[nt][0] + bk0);
            smu[OFF_K + (ebk + qr) * SK + bcol + 1]     = f2t(kD[nt][1] + bk0);
            smu[OFF_K + (ebk + qr + 8) * SK + bcol]     = f2t(kD[nt][2] + bk1);
            smu[OFF_K + (ebk + qr + 8) * SK + bcol + 1] = f2t(kD[nt][3] + bk1);
            smu[OFF_V + bcol * SV + ebk + qr]           = f2t(vD[nt][0] + bv0);
            smu[OFF_V + (bcol + 1) * SV + ebk + qr]     = f2t(vD[nt][1] + bv0);
            smu[OFF_V + bcol * SV + ebk + qr + 8]       = f2t(vD[nt][2] + bv1);
            smu[OFF_V + (bcol + 1) * SV + ebk + qr + 8] = f2t(vD[nt][3] + bv1);
        }
        __syncthreads();

        // ======== phase 2: scores tile-streamed; E~ = exp(scores*scale) ========
        float s0 = 0.0f, s1 = 0.0f;
        {
            uint32_t a0[4], a1[4];
            a0[0] = smu[OFF_K + (ebk + qr) * SK + qc];
            a0[1] = smu[OFF_K + (ebk + qr + 8) * SK + qc];
            a0[2] = smu[OFF_K + (ebk + qr) * SK + qc + 4];
            a0[3] = smu[OFF_K + (ebk + qr + 8) * SK + qc + 4];
            a1[0] = smu[OFF_K + (ebk + qr) * SK + 8 + qc];
            a1[1] = smu[OFF_K + (ebk + qr + 8) * SK + 8 + qc];
            a1[2] = smu[OFF_K + (ebk + qr) * SK + 8 + qc + 4];
            a1[3] = smu[OFF_K + (ebk + qr + 8) * SK + 8 + qc + 4];
            #pragma unroll
            for (int nt = 0; nt < 16; nt++) {
                float S4[4] = {0, 0, 0, 0};
                uint32_t b[2];
                b[0] = smu[OFF_V + qc * SV + nt * 8 + qr];
                b[1] = smu[OFF_V + (qc + 4) * SV + nt * 8 + qr];
                mma8(S4, a0, b);
                b[0] = smu[OFF_V + (8 + qc) * SV + nt * 8 + qr];
                b[1] = smu[OFF_V + (8 + qc + 4) * SV + nt * 8 + qr];
                mma8(S4, a1, b);
                const float e0 = ex2f(S4[0] * C2), e1 = ex2f(S4[1] * C2);
                const float e2 = ex2f(S4[2] * C2), e3 = ex2f(S4[3] * C2);
                s0 += e0 + e1;
                s1 += e2 + e3;
                uint2 p0 = { f2t(e0), f2t(e1) };
                *reinterpret_cast<uint2*>(&smu[OFF_E + (ebk + qr) * SE + nt * 8 + 2 * qc]) = p0;
                uint2 p1 = { f2t(e2), f2t(e3) };
                *reinterpret_cast<uint2*>(&smu[OFF_E + (ebk + qr + 8) * SE + nt * 8 + 2 * qc]) = p1;
            }
        }
        // row sums over qc group -> inv to smem
        s0 += __shfl_xor_sync(0xffffffffu, s0, 1);
        s0 += __shfl_xor_sync(0xffffffffu, s0, 2);
        s1 += __shfl_xor_sync(0xffffffffu, s1, 1);
        s1 += __shfl_xor_sync(0xffffffffu, s1, 2);
        if (qc == 0) {
            sm[OFF_INV + ebk + qr]     = 1.0f / s0;
            sm[OFF_INV + ebk + qr + 8] = 1.0f / s1;
        }
        __syncthreads();

        // ======== phase 3: O = x @ E~^T, then scale cols by inv[e] ========
        float O[2][4] = {{0,0,0,0},{0,0,0,0}};
        #pragma unroll
        for (int kk = 0; kk < 16; kk++) {
            const int fb = kk * 8;
            uint32_t a[4];
            a[0] = smu[OFF_X + qr * SX + fb + qc];
            a[1] = smu[OFF_X + (qr + 8) * SX + fb + qc];
            a[2] = smu[OFF_X + qr * SX + fb + qc + 4];
            a[3] = smu[OFF_X + (qr + 8) * SX + fb + qc + 4];
            uint32_t bn0[2], bn1[2];
            bn0[0] = smu[OFF_E + (ebk + qr) * SE + fb + qc];
            bn0[1] = smu[OFF_E + (ebk + qr) * SE + fb + qc + 4];
            bn1[0] = smu[OFF_E + (ebk + 8 + qr) * SE + fb + qc];
            bn1[1] = smu[OFF_E + (ebk + 8 + qr) * SE + fb + qc + 4];
            mma8(O[0], a, bn0); mma8(O[1], a, bn1);
        }
        // write out[s][b][e]: rows b = qr / qr+8, cols e = ebk + nt*8 + 2qc
        {
            float* op = out + (size_t)s * 2048;
            #pragma unroll
            for (int nt = 0; nt < 2; nt++) {
                const int ec = ebk + nt * 8 + 2 * qc;
                const float ia = sm[OFF_INV + ec];
                const float ib = sm[OFF_INV + ec + 1];
                *reinterpret_cast<float2*>(&op[qr * 128 + ec]) =
                    make_float2(O[nt][0] * ia, O[nt][1] * ib);
                *reinterpret_cast<float2*>(&op[(qr + 8) * 128 + ec]) =
                    make_float2(O[nt][2] * ia, O[nt][3] * ib);
            }
        }
        __syncthreads();  // protect x/E/inv from next-iter overwrites
        s = snext;
    }
}

extern "C" void kernel_launch(void* const* d_in, const int* in_sizes, int n_in,
                              void* d_out, int out_size) {
    const float* x  = (const float*)d_in[0];
    const float* Wk = (const float*)d_in[1];
    const float* bk = (const float*)d_in[2];
    const float* Wv = (const float*)d_in[3];
    const float* bv = (const float*)d_in[4];
    float* out = (float*)d_out;

    int sms = 148;
    cudaDeviceGetAttribute(&sms, cudaDevAttrMultiProcessorCount, 0);
    if (sms <= 0) sms = 148;
    cudaFuncSetAttribute(nsa_mma, cudaFuncAttributeMaxDynamicSharedMemorySize, SMEM_BYTES);
    nsa_mma<<<sms, 256, SMEM_BYTES>>>(x, Wk, bk, Wv, bv, out);
}

// round 11
// speedup vs baseline: 1.0411x; 1.0411x over previous
#include <cuda_runtime.h>
#include <cstdint>

// NativeSparseAttention: S=8192, B=16, E=128, fp32
// Persistent kernel, warp-level tf32 mma.sync (m16n8k8), 256 threads, 1 CTA/SM.
// R10 = R7 (champion) + fragment-major smem layouts (conflict-free LDS.128
// fragment loads for W, x, E). Math identical to R7.

#define S_TOTAL 8192

// fragment tile stride (floats): 32 lanes * 4 slots + 4 pad, 16B-aligned
#define FP 132

// smem offsets (floats)
#define OFF_WF  0                      // 8 warps x 2 mats x 16 kk x FP = 33792
#define OFF_X   33792                  // 16 kk x FP = 2112
#define OFF_K   35904                  // 128 x 20 = 2560
#define OFF_V   38464                  // 16 x 136 = 2176
#define OFF_INV 40640                  // 128
#define OFF_E   40768                  // 8 warps x 16 nt x FP = 16896
#define SMEM_FLOATS 57664
#define SMEM_BYTES  (SMEM_FLOATS * 4)  // 230656

#define SK 20
#define SV 136

__device__ __forceinline__ uint32_t f2t(float f) {
    uint32_t u; asm("cvt.rna.tf32.f32 %0, %1;" : "=r"(u) : "f"(f)); return u;
}
__device__ __forceinline__ float ex2f(float x) {
    float y; asm("ex2.approx.f32 %0, %1;" : "=f"(y) : "f"(x)); return y;
}
__device__ __forceinline__ void mma8(float* d, const uint32_t* a, const uint32_t* b) {
    asm volatile(
        "mma.sync.aligned.m16n8k8.row.col.f32.tf32.tf32.f32 "
        "{%0,%1,%2,%3}, {%4,%5,%6,%7}, {%8,%9}, {%0,%1,%2,%3};"
        : "+f"(d[0]), "+f"(d[1]), "+f"(d[2]), "+f"(d[3])
        : "r"(a[0]), "r"(a[1]), "r"(a[2]), "r"(a[3]), "r"(b[0]), "r"(b[1]));
}

__global__ __launch_bounds__(256, 1)
void nsa_mma(const float* __restrict__ x,
             const float* __restrict__ Wk,
             const float* __restrict__ bk,
             const float* __restrict__ Wv,
             const float* __restrict__ bv,
             float* __restrict__ out) {
    extern __shared__ float sm[];
    uint32_t* smu = reinterpret_cast<uint32_t*>(sm);

    const int t = threadIdx.x;
    const int wid = t >> 5;
    const int lid = t & 31;
    const int qr = lid >> 2;    // groupID 0..7
    const int qc = lid & 3;     // threadID-in-group 0..3
    const int ebk = wid * 16;   // warp's e-block base

    // ---- startup: stage Wk/Wv into per-warp fragment-major quads ----
    // two rounds, bouncing through the E region (128 x FP temp)
    #pragma unroll
    for (int m = 0; m < 2; m++) {
        const float4* Wg = reinterpret_cast<const float4*>(m ? Wv : Wk);
        #pragma unroll
        for (int i = 0; i < 16; i++) {
            const int l = t + 256 * i;          // float4 index over 128x128
            const int r = l >> 5, c = (l & 31) * 4;
            float4 a = Wg[l];
            uint4 pa = { f2t(a.x), f2t(a.y), f2t(a.z), f2t(a.w) };
            *reinterpret_cast<uint4*>(&smu[OFF_E + r * FP + c]) = pa;
        }
        __syncthreads();
        #pragma unroll
        for (int kk = 0; kk < 16; kk++) {
            const int jb = kk * 8;
            uint4 q;
            q.x = smu[OFF_E + (ebk + qr) * FP + jb + qc];
            q.y = smu[OFF_E + (ebk + qr + 8) * FP + jb + qc];
            q.z = smu[OFF_E + (ebk + qr) * FP + jb + qc + 4];
            q.w = smu[OFF_E + (ebk + qr + 8) * FP + jb + qc + 4];
            *reinterpret_cast<uint4*>(
                &smu[OFF_WF + wid * (2 * 16 * FP) + m * (16 * FP) + kk * FP + lid * 4]) = q;
        }
        __syncthreads();
    }

    const float bk0 = __ldg(bk + ebk + qr), bk1 = __ldg(bk + ebk + qr + 8);
    const float bv0 = __ldg(bv + ebk + qr), bv1 = __ldg(bv + ebk + qr + 8);
    const float C2 = 0.015939678942f;       // log2(e)/sqrt(8192)
    const int wfk = OFF_WF + wid * (2 * 16 * FP);
    const int wfv = wfk + 16 * FP;
    const int efb = OFF_E + wid * (16 * FP);

    int s = blockIdx.x;
    float4 xr0, xr1;
    if (s < S_TOTAL) {
        const float4* xg = reinterpret_cast<const float4*>(x + (size_t)s * 2048);
        xr0 = xg[t]; xr1 = xg[t + 256];
    }

    while (s < S_TOTAL) {
        // ---- stage x (tf32) into fragment-major XFRAG ----
        // value x[b][j]: kk=j/8, slot = 2*(b>=8) + ((j%8)>=4), lane = (b%8)*4 + j%4
        {
            const int m0 = (t & 31) >> 1;        // kk for this thread's float4s
            const int p0 = (t & 1);              // hi4 of j-chunk
            const int wrow = t >> 5;             // b of first float4 (0..7)
            const int base0 = OFF_X + m0 * FP + (wrow & 7) * 16 + p0;      // b<8 -> slot base 0
            smu[base0 + 0]  = f2t(xr0.x);
            smu[base0 + 4]  = f2t(xr0.y);
            smu[base0 + 8]  = f2t(xr0.z);
            smu[base0 + 12] = f2t(xr0.w);
            const int base1 = base0 + 2;                                    // b>=8 -> slot +2
            smu[base1 + 0]  = f2t(xr1.x);
            smu[base1 + 4]  = f2t(xr1.y);
            smu[base1 + 8]  = f2t(xr1.z);
            smu[base1 + 12] = f2t(xr1.w);
        }
        __syncthreads();

        // ---- prefetch next x into regs ----
        const int snext = s + gridDim.x;
        if (snext < S_TOTAL) {
            const float4* xg = reinterpret_cast<const float4*>(x + (size_t)snext * 2048);
            xr0 = xg[t]; xr1 = xg[t + 256];
        }

        // ======== phase 1: kT = Wk@xT, vT = Wv@xT  (M=e16, N=b16, K=128) ========
        // xf quad: {x[qr][jb+qc], x[qr][jb+qc+4], x[qr+8][jb+qc], x[qr+8][jb+qc+4]}
        uint4 xf[16];
        float kD[2][4] = {{0,0,0,0},{0,0,0,0}};
        float vD[2][4] = {{0,0,0,0},{0,0,0,0}};
        #pragma unroll
        for (int kk = 0; kk < 16; kk++) {
            const uint4 aK = *reinterpret_cast<const uint4*>(&smu[wfk + kk * FP + lid * 4]);
            const uint4 aV = *reinterpret_cast<const uint4*>(&smu[wfv + kk * FP + lid * 4]);
            xf[kk] = *reinterpret_cast<const uint4*>(&smu[OFF_X + kk * FP + lid * 4]);
            mma8(kD[0], &aK.x, &xf[kk].x); mma8(kD[1], &aK.x, &xf[kk].z);
            mma8(vD[0], &aV.x, &xf[kk].x); mma8(vD[1], &aV.x, &xf[kk].z);
        }
        // store k as [e][b] (stride SK), v as [b][f] (stride SV), +bias, tf32
        #pragma unroll
        for (int nt = 0; nt < 2; nt++) {
            const int bcol = nt * 8 + 2 * qc;
            smu[OFF_K + (ebk + qr) * SK + bcol]         = f2t(kD[nt][0] + bk0);
            smu[OFF_K + (ebk + qr) * SK + bcol + 1]     = f2t(kD[nt][1] + bk0);
            smu[OFF_K + (ebk + qr + 8) * SK + bcol]     = f2t(kD[nt][2] + bk1);
            smu[OFF_K + (ebk + qr + 8) * SK + bcol + 1] = f2t(kD[nt][3] + bk1);
            smu[OFF_V + bcol * SV + ebk + qr]           = f2t(vD[nt][0] + bv0);
            smu[OFF_V + (bcol + 1) * SV + ebk + qr]     = f2t(vD[nt][1] + bv0);
            smu[OFF_V + bcol * SV + ebk + qr + 8]       = f2t(vD[nt][2] + bv1);
            smu[OFF_V + (bcol + 1) * SV + ebk + qr + 8] = f2t(vD[nt][3] + bv1);
        }
        __syncthreads();

        // ======== phase 2: scores = kT @ vT^T  (M=e16, N=f128, K=16) ========
        float s0 = 0.0f, s1 = 0.0f;
        {
            uint32_t a0[4], a1[4];
            a0[0] = smu[OFF_K + (ebk + qr) * SK + qc];
            a0[1] = smu[OFF_K + (ebk + qr + 8) * SK + qc];
            a0[2] = smu[OFF_K + (ebk + qr) * SK + qc + 4];
            a0[3] = smu[OFF_K + (ebk + qr + 8) * SK + qc + 4];
            a1[0] = smu[OFF_K + (ebk + qr) * SK + 8 + qc];
            a1[1] = smu[OFF_K + (ebk + qr + 8) * SK + 8 + qc];
            a1[2] = smu[OFF_K + (ebk + qr) * SK + 8 + qc + 4];
            a1[3] = smu[OFF_K + (ebk + qr + 8) * SK + 8 + qc + 4];
            // E store slots: lane = (row%8)*4 + col8%4, slot = 2*(row>=8) + (col8>=4)
            const int sl = (qc >= 2) ? 1 : 0;
            const int l0 = (qr * 4 + ((2 * qc) & 3)) * 4 + sl;       // col8 = 2qc
            const int l1 = (qr * 4 + ((2 * qc + 1) & 3)) * 4 + sl;   // col8 = 2qc+1
            #pragma unroll
            for (int nt = 0; nt < 16; nt++) {
                float S4[4] = {0, 0, 0, 0};
                uint32_t b[2];
                b[0] = smu[OFF_V + qc * SV + nt * 8 + qr];
                b[1] = smu[OFF_V + (qc + 4) * SV + nt * 8 + qr];
                mma8(S4, a0, b);
                b[0] = smu[OFF_V + (8 + qc) * SV + nt * 8 + qr];
                b[1] = smu[OFF_V + (8 + qc + 4) * SV + nt * 8 + qr];
                mma8(S4, a1, b);
                const float e0 = ex2f(S4[0] * C2), e1 = ex2f(S4[1] * C2);
                const float e2 = ex2f(S4[2] * C2), e3 = ex2f(S4[3] * C2);
                s0 += e0 + e1;
                s1 += e2 + e3;
                const int eb = efb + nt * FP;
                smu[eb + l0]     = f2t(e0);
                smu[eb + l1]     = f2t(e1);
                smu[eb + l0 + 2] = f2t(e2);
                smu[eb + l1 + 2] = f2t(e3);
            }
        }
        // row sums over qc group -> inv to smem
        s0 += __shfl_xor_sync(0xffffffffu, s0, 1);
        s0 += __shfl_xor_sync(0xffffffffu, s0, 2);
        s1 += __shfl_xor_sync(0xffffffffu, s1, 1);
        s1 += __shfl_xor_sync(0xffffffffu, s1, 2);
        const float i0 = 1.0f / s0, i1 = 1.0f / s1;
        if (qc == 0) {
            sm[OFF_INV + ebk + qr]     = i0;
            sm[OFF_INV + ebk + qr + 8] = i1;
        }
        __syncthreads();

        // ======== phase 3: O = x @ E~^T, scale cols by inv[e] ========
        float O[2][4] = {{0,0,0,0},{0,0,0,0}};
        #pragma unroll
        for (int kk = 0; kk < 16; kk++) {
            const uint4 eq = *reinterpret_cast<const uint4*>(&smu[efb + kk * FP + lid * 4]);
            const uint32_t a[4] = { xf[kk].x, xf[kk].z, xf[kk].y, xf[kk].w };
            mma8(O[0], a, &eq.x); mma8(O[1], a, &eq.z);
        }
        // write out[s][b][e]: rows b = qr / qr+8, cols e = ebk + nt*8 + 2qc
        {
            float* op = out + (size_t)s * 2048;
            #pragma unroll
            for (int nt = 0; nt < 2; nt++) {
                const int ec = ebk + nt * 8 + 2 * qc;
                const float ia = sm[OFF_INV + ec];
                const float ib = sm[OFF_INV + ec + 1];
                *reinterpret_cast<float2*>(&op[qr * 128 + ec]) =
                    make_float2(O[nt][0] * ia, O[nt][1] * ib);
                *reinterpret_cast<float2*>(&op[(qr + 8) * 128 + ec]) =
                    make_float2(O[nt][2] * ia, O[nt][3] * ib);
            }
        }
        __syncthreads();  // protect x/E/inv from next-iter overwrites
        s = snext;
    }
}

extern "C" void kernel_launch(void* const* d_in, const int* in_sizes, int n_in,
                              void* d_out, int out_size) {
    const float* x  = (const float*)d_in[0];
    const float* Wk = (const float*)d_in[1];
    const float* bk = (const float*)d_in[2];
    const float* Wv = (const float*)d_in[3];
    const float* bv = (const float*)d_in[4];
    float* out = (float*)d_out;

    int sms = 148;
    cudaDeviceGetAttribute(&sms, cudaDevAttrMultiProcessorCount, 0);
    if (sms <= 0) sms = 148;
    cudaFuncSetAttribute(nsa_mma, cudaFuncAttributeMaxDynamicSharedMemorySize, SMEM_BYTES);
    nsa_mma<<<sms, 256, SMEM_BYTES>>>(x, Wk, bk, Wv, bv, out);
}

// round 12
// speedup vs baseline: 1.1771x; 1.1306x over previous
#include <cuda_runtime.h>
#include <cstdint>

// NativeSparseAttention: S=8192, B=16, E=128, fp32
// Persistent kernel, warp-level tf32 mma.sync (m16n8k8), 256 threads, 1 CTA/SM.
// R11 = R7 (champion) with x/E smem strides 136 -> 132: removes the 2-way
// bank conflicts on all x-fragment and E-fragment loads. Math identical.

#define S_TOTAL 8192

// strides (floats)
#define SW 132    // W: bank = 4*qr+qc  -> conflict-free
#define SX 132    // x: bank = 4*qr+qc  -> conflict-free (was 136: 2-way)
#define SK 20     // k: bank = 20*qr+qc -> conflict-free
#define SV 136    // v: bank = 8*qc+qr  -> conflict-free (132 would conflict)
#define SE 132    // E: bank = 4*qr+qc  -> conflict-free loads (was 136: 2-way)

// smem offsets (floats)
#define OFF_WK 0
#define OFF_WV (128 * SW)                 // 16896
#define OFF_XH (OFF_WV + 128 * SW)        // 33792
#define OFF_K  (OFF_XH + 16 * SX)         // 35904
#define OFF_V  (OFF_K + 128 * SK)         // 38464
#define OFF_E  (OFF_K)                    // aliases k/v (dead by then); 128*SE=16896
#define SMEM_FLOATS (OFF_E + 128 * SE)    // 52800
#define SMEM_BYTES  (SMEM_FLOATS * 4)     // 211200

__device__ __forceinline__ uint32_t f2t(float f) {
    uint32_t u; asm("cvt.rna.tf32.f32 %0, %1;" : "=r"(u) : "f"(f)); return u;
}
__device__ __forceinline__ float ex2f(float x) {
    float y; asm("ex2.approx.f32 %0, %1;" : "=f"(y) : "f"(x)); return y;
}
__device__ __forceinline__ void mma8(float* d, const uint32_t* a, const uint32_t* b) {
    asm volatile(
        "mma.sync.aligned.m16n8k8.row.col.f32.tf32.tf32.f32 "
        "{%0,%1,%2,%3}, {%4,%5,%6,%7}, {%8,%9}, {%0,%1,%2,%3};"
        : "+f"(d[0]), "+f"(d[1]), "+f"(d[2]), "+f"(d[3])
        : "r"(a[0]), "r"(a[1]), "r"(a[2]), "r"(a[3]), "r"(b[0]), "r"(b[1]));
}

__global__ __launch_bounds__(256, 1)
void nsa_mma(const float* __restrict__ x,
             const float* __restrict__ Wk,
             const float* __restrict__ bk,
             const float* __restrict__ Wv,
             const float* __restrict__ bv,
             float* __restrict__ out) {
    extern __shared__ float sm[];
    uint32_t* smu = reinterpret_cast<uint32_t*>(sm);

    const int t = threadIdx.x;
    const int wid = t >> 5;
    const int lid = t & 31;
    const int qr = lid >> 2;    // groupID 0..7
    const int qc = lid & 3;     // threadID-in-group 0..3
    const int ebk = wid * 16;   // warp's e-block base

    // ---- one-time: stage Wk/Wv as tf32, row-major stride SW ----
    #pragma unroll
    for (int i = 0; i < 16; i++) {
        const int l = t + 256 * i;          // float4 index over 128x128
        const int r = l >> 5, c = (l & 31) * 4;
        float4 a = reinterpret_cast<const float4*>(Wk)[l];
        uint4 pa = { f2t(a.x), f2t(a.y), f2t(a.z), f2t(a.w) };
        *reinterpret_cast<uint4*>(&smu[OFF_WK + r * SW + c]) = pa;
        float4 b = reinterpret_cast<const float4*>(Wv)[l];
        uint4 pb = { f2t(b.x), f2t(b.y), f2t(b.z), f2t(b.w) };
        *reinterpret_cast<uint4*>(&smu[OFF_WV + r * SW + c]) = pb;
    }
    const float bk0 = __ldg(bk + ebk + qr), bk1 = __ldg(bk + ebk + qr + 8);
    const float bv0 = __ldg(bv + ebk + qr), bv1 = __ldg(bv + ebk + qr + 8);
    const float C2 = 0.015939678942f;       // log2(e)/sqrt(8192)

    int s = blockIdx.x;
    float4 xr0, xr1;
    if (s < S_TOTAL) {
        const float4* xg = reinterpret_cast<const float4*>(x + (size_t)s * 2048);
        xr0 = xg[t]; xr1 = xg[t + 256];
    }
    __syncthreads();

    while (s < S_TOTAL) {
        // ---- stage x (tf32) into [b][j] stride SX ----
        {
            const int b0i = t >> 5,         c0 = (t & 31) * 4;
            const int b1i = (t + 256) >> 5, c1 = ((t + 256) & 31) * 4;
            uint4 h;
            h.x = f2t(xr0.x); h.y = f2t(xr0.y); h.z = f2t(xr0.z); h.w = f2t(xr0.w);
            *reinterpret_cast<uint4*>(&smu[OFF_XH + b0i * SX + c0]) = h;
            h.x = f2t(xr1.x); h.y = f2t(xr1.y); h.z = f2t(xr1.z); h.w = f2t(xr1.w);
            *reinterpret_cast<uint4*>(&smu[OFF_XH + b1i * SX + c1]) = h;
        }
        __syncthreads();

        // ---- prefetch next x into regs ----
        const int snext = s + gridDim.x;
        if (snext < S_TOTAL) {
            const float4* xg = reinterpret_cast<const float4*>(x + (size_t)snext * 2048);
            xr0 = xg[t]; xr1 = xg[t + 256];
        }

        // ======== phase 1: kT = Wk@xT, vT = Wv@xT  (M=e16, N=b16, K=128) ========
        // x fragments kept in registers for reuse as phase-3 A operands:
        // xf[kk] = { x[qr][jb+qc], x[qr][jb+qc+4], x[qr+8][jb+qc], x[qr+8][jb+qc+4] }
        uint32_t xf[16][4];
        float kD[2][4] = {{0,0,0,0},{0,0,0,0}};
        float vD[2][4] = {{0,0,0,0},{0,0,0,0}};
        #pragma unroll
        for (int kk = 0; kk < 16; kk++) {
            const int jb = kk * 8;
            uint32_t aK[4], aV[4];
            aK[0] = smu[OFF_WK + (ebk + qr) * SW + jb + qc];
            aK[1] = smu[OFF_WK + (ebk + qr + 8) * SW + jb + qc];
            aK[2] = smu[OFF_WK + (ebk + qr) * SW + jb + qc + 4];
            aK[3] = smu[OFF_WK + (ebk + qr + 8) * SW + jb + qc + 4];
            aV[0] = smu[OFF_WV + (ebk + qr) * SW + jb + qc];
            aV[1] = smu[OFF_WV + (ebk + qr + 8) * SW + jb + qc];
            aV[2] = smu[OFF_WV + (ebk + qr) * SW + jb + qc + 4];
            aV[3] = smu[OFF_WV + (ebk + qr + 8) * SW + jb + qc + 4];
            xf[kk][0] = smu[OFF_XH + qr * SX + jb + qc];
            xf[kk][1] = smu[OFF_XH + qr * SX + jb + qc + 4];
            xf[kk][2] = smu[OFF_XH + (qr + 8) * SX + jb + qc];
            xf[kk][3] = smu[OFF_XH + (qr + 8) * SX + jb + qc + 4];
            mma8(kD[0], aK, &xf[kk][0]); mma8(kD[1], aK, &xf[kk][2]);
            mma8(vD[0], aV, &xf[kk][0]); mma8(vD[1], aV, &xf[kk][2]);
        }
        // store k as [e][b] (stride SK), v as [b][f] (stride SV), +bias, tf32
        #pragma unroll
        for (int nt = 0; nt < 2; nt++) {
            const int bcol = nt * 8 + 2 * qc;
            smu[OFF_K + (ebk + qr) * SK + bcol]         = f2t(kD[nt][0] + bk0);
            smu[OFF_K + (ebk + qr) * SK + bcol + 1]     = f2t(kD[nt][1] + bk0);
            smu[OFF_K + (ebk + qr + 8) * SK + bcol]     = f2t(kD[nt][2] + bk1);
            smu[OFF_K + (ebk + qr + 8) * SK + bcol + 1] = f2t(kD[nt][3] + bk1);
            smu[OFF_V + bcol * SV + ebk + qr]           = f2t(vD[nt][0] + bv0);
            smu[OFF_V + (bcol + 1) * SV + ebk + qr]     = f2t(vD[nt][1] + bv0);
            smu[OFF_V + bcol * SV + ebk + qr + 8]       = f2t(vD[nt][2] + bv1);
            smu[OFF_V + (bcol + 1) * SV + ebk + qr + 8] = f2t(vD[nt][3] + bv1);
        }
        __syncthreads();

        // ======== phase 2: scores = kT @ vT^T  (M=e16, N=f128, K=16) ========
        float S[16][4];
        #pragma unroll
        for (int nt = 0; nt < 16; nt++) { S[nt][0] = S[nt][1] = S[nt][2] = S[nt][3] = 0.0f; }
        #pragma unroll
        for (int kk = 0; kk < 2; kk++) {
            const int bb = kk * 8;
            uint32_t a[4];
            a[0] = smu[OFF_K + (ebk + qr) * SK + bb + qc];
            a[1] = smu[OFF_K + (ebk + qr + 8) * SK + bb + qc];
            a[2] = smu[OFF_K + (ebk + qr) * SK + bb + qc + 4];
            a[3] = smu[OFF_K + (ebk + qr + 8) * SK + bb + qc + 4];
            #pragma unroll
            for (int nt = 0; nt < 16; nt++) {
                uint32_t b[2];
                b[0] = smu[OFF_V + (bb + qc) * SV + nt * 8 + qr];
                b[1] = smu[OFF_V + (bb + qc + 4) * SV + nt * 8 + qr];
                mma8(S[nt], a, b);
            }
        }

        // ---- softmax (no max-sub; |arg| small), normalize into E ----
        float s0 = 0.0f, s1 = 0.0f;
        #pragma unroll
        for (int nt = 0; nt < 16; nt++) {
            S[nt][0] = ex2f(S[nt][0] * C2); S[nt][1] = ex2f(S[nt][1] * C2);
            S[nt][2] = ex2f(S[nt][2] * C2); S[nt][3] = ex2f(S[nt][3] * C2);
            s0 += S[nt][0] + S[nt][1];
            s1 += S[nt][2] + S[nt][3];
        }
        s0 += __shfl_xor_sync(0xffffffffu, s0, 1);
        s0 += __shfl_xor_sync(0xffffffffu, s0, 2);
        s1 += __shfl_xor_sync(0xffffffffu, s1, 1);
        s1 += __shfl_xor_sync(0xffffffffu, s1, 2);
        const float i0 = 1.0f / s0, i1 = 1.0f / s1;

        __syncthreads();  // all k/v reads done before E overwrites the region

        #pragma unroll
        for (int nt = 0; nt < 16; nt++) {
            uint2 p0 = { f2t(S[nt][0] * i0), f2t(S[nt][1] * i0) };
            *reinterpret_cast<uint2*>(&smu[OFF_E + (ebk + qr) * SE + nt * 8 + 2 * qc]) = p0;
            uint2 p1 = { f2t(S[nt][2] * i1), f2t(S[nt][3] * i1) };
            *reinterpret_cast<uint2*>(&smu[OFF_E + (ebk + qr + 8) * SE + nt * 8 + 2 * qc]) = p1;
        }
        __syncthreads();

        // ======== phase 3: O = x @ E^T  (M=b16, N=e16 per warp, K=128) ========
        // A operands come straight from xf (permutation of phase-1 B fragments).
        float O[2][4] = {{0,0,0,0},{0,0,0,0}};
        #pragma unroll
        for (int kk = 0; kk < 16; kk++) {
            const int fb = kk * 8;
            const uint32_t a[4] = { xf[kk][0], xf[kk][2], xf[kk][1], xf[kk][3] };
            uint32_t bn0[2], bn1[2];
            bn0[0] = smu[OFF_E + (ebk + qr) * SE + fb + qc];
            bn0[1] = smu[OFF_E + (ebk + qr) * SE + fb + qc + 4];
            bn1[0] = smu[OFF_E + (ebk + 8 + qr) * SE + fb + qc];
            bn1[1] = smu[OFF_E + (ebk + 8 + qr) * SE + fb + qc + 4];
            mma8(O[0], a, bn0); mma8(O[1], a, bn1);
        }
        // write out[s][b][e]: rows b = qr / qr+8, cols e = ebk + nt*8 + 2qc
        {
            float* op = out + (size_t)s * 2048;
            #pragma unroll
            for (int nt = 0; nt < 2; nt++) {
                const int ec = ebk + nt * 8 + 2 * qc;
                *reinterpret_cast<float2*>(&op[qr * 128 + ec])       = make_float2(O[nt][0], O[nt][1]);
                *reinterpret_cast<float2*>(&op[(qr + 8) * 128 + ec]) = make_float2(O[nt][2], O[nt][3]);
            }
        }
        __syncthreads();  // protect xh and E from next-iter overwrites
        s = snext;
    }
}

extern "C" void kernel_launch(void* const* d_in, const int* in_sizes, int n_in,
                              void* d_out, int out_size) {
    const float* x  = (const float*)d_in[0];
    const float* Wk = (const float*)d_in[1];
    const float* bk = (const float*)d_in[2];
    const float* Wv = (const float*)d_in[3];
    const float* bv = (const float*)d_in[4];
    float* out = (float*)d_out;

    int sms = 148;
    cudaDeviceGetAttribute(&sms, cudaDevAttrMultiProcessorCount, 0);
    if (sms <= 0) sms = 148;
    cudaFuncSetAttribute(nsa_mma, cudaFuncAttributeMaxDynamicSharedMemorySize, SMEM_BYTES);
    nsa_mma<<<sms, 256, SMEM_BYTES>>>(x, Wk, bk, Wv, bv, out);
}

// round 13
// speedup vs baseline: 1.4707x; 1.2494x over previous
#include <cuda_runtime.h>
#include <cstdint>

// NativeSparseAttention: S=8192, B=16, E=128, fp32
// Persistent kernel, warp-level tf32 mma.sync (m16n8k8), 256 threads, 1 CTA/SM.
// R12: fragment-permutation fusion. sigma(j)=(j>>1)+4*(j&1) applied to P1's
// b-columns and P2's f-columns makes producer D-fragments identical to
// consumer A/B-fragments: k stays in registers (P1->P2), E stays in
// registers (P2->P3, fused loop). Normalization in epilogue (R8 numerics).

#define S_TOTAL 8192

// strides (floats)
#define SW 132    // W: bank 4*qr+qc          -> conflict-free
#define SX 132    // x: bank 4*sigma(qr)+qc   -> conflict-free
#define SV 136    // v: bank 8*qc+sigma(qr)   -> conflict-free

// smem offsets (floats)
#define OFF_WK  0
#define OFF_WV  (128 * SW)                // 16896
#define OFF_XH  (OFF_WV + 128 * SW)       // 33792
#define OFF_V   (OFF_XH + 16 * SX)        // 35904 ; 16 x 136 = 2176
#define OFF_INV (OFF_V + 16 * SV)         // 38080
#define SMEM_FLOATS (OFF_INV + 128)       // 38208
#define SMEM_BYTES  (SMEM_FLOATS * 4)     // 152832

__device__ __forceinline__ uint32_t f2t(float f) {
    uint32_t u; asm("cvt.rna.tf32.f32 %0, %1;" : "=r"(u) : "f"(f)); return u;
}
__device__ __forceinline__ float ex2f(float x) {
    float y; asm("ex2.approx.f32 %0, %1;" : "=f"(y) : "f"(x)); return y;
}
__device__ __forceinline__ void mma8(float* d, const uint32_t* a, const uint32_t* b) {
    asm volatile(
        "mma.sync.aligned.m16n8k8.row.col.f32.tf32.tf32.f32 "
        "{%0,%1,%2,%3}, {%4,%5,%6,%7}, {%8,%9}, {%0,%1,%2,%3};"
        : "+f"(d[0]), "+f"(d[1]), "+f"(d[2]), "+f"(d[3])
        : "r"(a[0]), "r"(a[1]), "r"(a[2]), "r"(a[3]), "r"(b[0]), "r"(b[1]));
}

__global__ __launch_bounds__(256, 1)
void nsa_mma(const float* __restrict__ x,
             const float* __restrict__ Wk,
             const float* __restrict__ bk,
             const float* __restrict__ Wv,
             const float* __restrict__ bv,
             float* __restrict__ out) {
    extern __shared__ float sm[];
    uint32_t* smu = reinterpret_cast<uint32_t*>(sm);

    const int t = threadIdx.x;
    const int wid = t >> 5;
    const int lid = t & 31;
    const int qr = lid >> 2;                    // groupID 0..7
    const int qc = lid & 3;                     // threadID-in-group 0..3
    const int sq = (qr >> 1) + 4 * (qr & 1);    // sigma(qr)
    const int ebk = wid * 16;                   // warp's e-block base

    // ---- one-time: stage Wk/Wv as tf32, row-major stride SW ----
    #pragma unroll
    for (int i = 0; i < 16; i++) {
        const int l = t + 256 * i;          // float4 index over 128x128
        const int r = l >> 5, c = (l & 31) * 4;
        float4 a = reinterpret_cast<const float4*>(Wk)[l];
        uint4 pa = { f2t(a.x), f2t(a.y), f2t(a.z), f2t(a.w) };
        *reinterpret_cast<uint4*>(&smu[OFF_WK + r * SW + c]) = pa;
        float4 b = reinterpret_cast<const float4*>(Wv)[l];
        uint4 pb = { f2t(b.x), f2t(b.y), f2t(b.z), f2t(b.w) };
        *reinterpret_cast<uint4*>(&smu[OFF_WV + r * SW + c]) = pb;
    }
    const float bk0 = __ldg(bk + ebk + qr), bk1 = __ldg(bk + ebk + qr + 8);
    const float bv0 = __ldg(bv + ebk + qr), bv1 = __ldg(bv + ebk + qr + 8);
    const float C2 = 0.015939678942f;       // log2(e)/sqrt(8192)

    int s = blockIdx.x;
    float4 xr0, xr1;
    if (s < S_TOTAL) {
        const float4* xg = reinterpret_cast<const float4*>(x + (size_t)s * 2048);
        xr0 = xg[t]; xr1 = xg[t + 256];
    }
    __syncthreads();

    while (s < S_TOTAL) {
        // ---- stage x (tf32) into [b][j] stride SX ----
        {
            const int b0i = t >> 5,         c0 = (t & 31) * 4;
            const int b1i = (t + 256) >> 5, c1 = ((t + 256) & 31) * 4;
            uint4 h;
            h.x = f2t(xr0.x); h.y = f2t(xr0.y); h.z = f2t(xr0.z); h.w = f2t(xr0.w);
            *reinterpret_cast<uint4*>(&smu[OFF_XH + b0i * SX + c0]) = h;
            h.x = f2t(xr1.x); h.y = f2t(xr1.y); h.z = f2t(xr1.z); h.w = f2t(xr1.w);
            *reinterpret_cast<uint4*>(&smu[OFF_XH + b1i * SX + c1]) = h;
        }
        __syncthreads();                        // (A)

        // ---- prefetch next x into regs ----
        const int snext = s + gridDim.x;
        if (snext < S_TOTAL) {
            const float4* xg = reinterpret_cast<const float4*>(x + (size_t)snext * 2048);
            xr0 = xg[t]; xr1 = xg[t + 256];
        }

        // ======== phase 1: kT = Wk@xT, vT = Wv@xT (M=e16, N=b16 sigma-mapped) ====
        // xf[kk] = { x[sq][jb+qc], x[sq][jb+qc+4], x[sq+8][jb+qc], x[sq+8][jb+qc+4] }
        // (B-fragments for P1 with n-pos qr -> global b = sigma(qr)(+8);
        //  reused as P3 A-fragments with m-pos qr -> out row b = sigma(qr)(+8))
        uint32_t xf[16][4];
        float kD[2][4] = {{0,0,0,0},{0,0,0,0}};
        float vD[2][4] = {{0,0,0,0},{0,0,0,0}};
        #pragma unroll
        for (int kk = 0; kk < 16; kk++) {
            const int jb = kk * 8;
            uint32_t aK[4], aV[4];
            aK[0] = smu[OFF_WK + (ebk + qr) * SW + jb + qc];
            aK[1] = smu[OFF_WK + (ebk + qr + 8) * SW + jb + qc];
            aK[2] = smu[OFF_WK + (ebk + qr) * SW + jb + qc + 4];
            aK[3] = smu[OFF_WK + (ebk + qr + 8) * SW + jb + qc + 4];
            aV[0] = smu[OFF_WV + (ebk + qr) * SW + jb + qc];
            aV[1] = smu[OFF_WV + (ebk + qr + 8) * SW + jb + qc];
            aV[2] = smu[OFF_WV + (ebk + qr) * SW + jb + qc + 4];
            aV[3] = smu[OFF_WV + (ebk + qr + 8) * SW + jb + qc + 4];
            xf[kk][0] = smu[OFF_XH + sq * SX + jb + qc];
            xf[kk][1] = smu[OFF_XH + sq * SX + jb + qc + 4];
            xf[kk][2] = smu[OFF_XH + (sq + 8) * SX + jb + qc];
            xf[kk][3] = smu[OFF_XH + (sq + 8) * SX + jb + qc + 4];
            mma8(kD[0], aK, &xf[kk][0]); mma8(kD[1], aK, &xf[kk][2]);
            mma8(vD[0], aV, &xf[kk][0]); mma8(vD[1], aV, &xf[kk][2]);
        }

        // k: straight into P2 A-fragments (registers; sigma makes layouts match)
        // kD[t][0]=k[qr][t8+qc], [1]=k[qr][t8+qc+4], [2]=k[qr+8][t8+qc], [3]=k[qr+8][t8+qc+4]
        uint32_t ka0[4], ka1[4];
        ka0[0] = f2t(kD[0][0] + bk0); ka0[1] = f2t(kD[0][2] + bk1);
        ka0[2] = f2t(kD[0][1] + bk0); ka0[3] = f2t(kD[0][3] + bk1);
        ka1[0] = f2t(kD[1][0] + bk0); ka1[1] = f2t(kD[1][2] + bk1);
        ka1[2] = f2t(kD[1][1] + bk0); ka1[3] = f2t(kD[1][3] + bk1);

        // v -> smem [b][f], b-cols sigma-mapped: thread holds b = nt*8+qc, +qc+4
        #pragma unroll
        for (int nt = 0; nt < 2; nt++) {
            const int b0c = nt * 8 + qc;
            smu[OFF_V + b0c * SV + ebk + qr]           = f2t(vD[nt][0] + bv0);
            smu[OFF_V + (b0c + 4) * SV + ebk + qr]     = f2t(vD[nt][1] + bv0);
            smu[OFF_V + b0c * SV + ebk + qr + 8]       = f2t(vD[nt][2] + bv1);
            smu[OFF_V + (b0c + 4) * SV + ebk + qr + 8] = f2t(vD[nt][3] + bv1);
        }
        __syncthreads();                        // (B)

        // ======== fused phase 2+3 per f-tile: scores->exp->O accumulate ========
        // P2 B n-pos qr -> f = nt*8 + sigma(qr)  =>  S4 cols are f = nt*8+qc, +qc+4
        // => S4 (after exp/f2t) IS P3's B-fragment for k-tile nt.
        float Oe[2][4] = {{0,0,0,0},{0,0,0,0}};
        float Oo[2][4] = {{0,0,0,0},{0,0,0,0}};
        float s0 = 0.0f, s1 = 0.0f;
        #pragma unroll
        for (int nt = 0; nt < 16; nt++) {
            float S4[4] = {0, 0, 0, 0};
            uint32_t b[2];
            b[0] = smu[OFF_V + qc * SV + nt * 8 + sq];
            b[1] = smu[OFF_V + (qc + 4) * SV + nt * 8 + sq];
            mma8(S4, ka0, b);
            b[0] = smu[OFF_V + (8 + qc) * SV + nt * 8 + sq];
            b[1] = smu[OFF_V + (8 + qc + 4) * SV + nt * 8 + sq];
            mma8(S4, ka1, b);
            const float e0 = ex2f(S4[0] * C2), e1 = ex2f(S4[1] * C2);
            const float e2 = ex2f(S4[2] * C2), e3 = ex2f(S4[3] * C2);
            s0 += e0 + e1;
            s1 += e2 + e3;
            uint32_t bf0[2] = { f2t(e0), f2t(e1) };
            uint32_t bf1[2] = { f2t(e2), f2t(e3) };
            const uint32_t a[4] = { xf[nt][0], xf[nt][2], xf[nt][1], xf[nt][3] };
            float* O0 = (nt & 1) ? Oo[0] : Oe[0];
            float* O1 = (nt & 1) ? Oo[1] : Oe[1];
            mma8(O0, a, bf0);
            mma8(O1, a, bf1);
        }

        // row sums (e = ebk+qr / +8) -> inv
        s0 += __shfl_xor_sync(0xffffffffu, s0, 1);
        s0 += __shfl_xor_sync(0xffffffffu, s0, 2);
        s1 += __shfl_xor_sync(0xffffffffu, s1, 1);
        s1 += __shfl_xor_sync(0xffffffffu, s1, 2);
        if (qc == 0) {
            sm[OFF_INV + ebk + qr]     = 1.0f / s0;
            sm[OFF_INV + ebk + qr + 8] = 1.0f / s1;
        }
        __syncthreads();                        // (C)

        // ======== epilogue: out[b=sigma(qr)(+8)][e] = O * inv[e] ========
        {
            float* op = out + (size_t)s * 2048;
            #pragma unroll
            for (int nt2 = 0; nt2 < 2; nt2++) {
                const int ec = ebk + nt2 * 8 + 2 * qc;
                const float ia = sm[OFF_INV + ec];
                const float ib = sm[OFF_INV + ec + 1];
                const float o0 = Oe[nt2][0] + Oo[nt2][0];
                const float o1 = Oe[nt2][1] + Oo[nt2][1];
                const float o2 = Oe[nt2][2] + Oo[nt2][2];
                const float o3 = Oe[nt2][3] + Oo[nt2][3];
                *reinterpret_cast<float2*>(&op[sq * 128 + ec]) =
                    make_float2(o0 * ia, o1 * ib);
                *reinterpret_cast<float2*>(&op[(sq + 8) * 128 + ec]) =
                    make_float2(o2 * ia, o3 * ib);
            }
        }
        s = snext;
    }
}

extern "C" void kernel_launch(void* const* d_in, const int* in_sizes, int n_in,
                              void* d_out, int out_size) {
    const float* x  = (const float*)d_in[0];
    const float* Wk = (const float*)d_in[1];
    const float* bk = (const float*)d_in[2];
    const float* Wv = (const float*)d_in[3];
    const float* bv = (const float*)d_in[4];
    float* out = (float*)d_out;

    int sms = 148;
    cudaDeviceGetAttribute(&sms, cudaDevAttrMultiProcessorCount, 0);
    if (sms <= 0) sms = 148;
    cudaFuncSetAttribute(nsa_mma, cudaFuncAttributeMaxDynamicSharedMemorySize, SMEM_BYTES);
    nsa_mma<<<sms, 256, SMEM_BYTES>>>(x, Wk, bk, Wv, bv, out);
}

// round 14
// speedup vs baseline: 1.5877x; 1.0795x over previous
#include <cuda_runtime.h>
#include <cstdint>

// NativeSparseAttention: S=8192, B=16, E=128, fp32
// Persistent kernel, warp-level tf32 mma.sync (m16n8k8).
// R13 = R12 fusion + 512 threads/CTA: two s per iteration (halves share the
// W smem tile), doubling occupancy 12.5% -> 25%. Hybrid xf cache (8 tiles in
// regs, 8 reloaded) to fit the 128-reg cap at 512 threads.

#define S_TOTAL 8192

// strides (floats)
#define SW 132    // W: bank 4*qr+qc          -> conflict-free
#define SX 132    // x: bank 4*sigma(qr)+qc   -> conflict-free
#define SV 136    // v: bank 8*qc+sigma(qr)   -> conflict-free

// smem offsets (floats)
#define OFF_WK  0
#define OFF_WV  (128 * SW)                 // 16896
#define OFF_X   (OFF_WV + 128 * SW)        // 33792 ; 2 halves x 16 x SX
#define OFF_V   (OFF_X + 2 * 16 * SX)      // 38016 ; 2 halves x 16 x SV
#define OFF_INV (OFF_V + 2 * 16 * SV)      // 42368 ; 2 halves x 128
#define SMEM_FLOATS (OFF_INV + 256)        // 42624
#define SMEM_BYTES  (SMEM_FLOATS * 4)      // 170496

__device__ __forceinline__ uint32_t f2t(float f) {
    uint32_t u; asm("cvt.rna.tf32.f32 %0, %1;" : "=r"(u) : "f"(f)); return u;
}
__device__ __forceinline__ float ex2f(float x) {
    float y; asm("ex2.approx.f32 %0, %1;" : "=f"(y) : "f"(x)); return y;
}
__device__ __forceinline__ void mma8(float* d, const uint32_t* a, const uint32_t* b) {
    asm volatile(
        "mma.sync.aligned.m16n8k8.row.col.f32.tf32.tf32.f32 "
        "{%0,%1,%2,%3}, {%4,%5,%6,%7}, {%8,%9}, {%0,%1,%2,%3};"
        : "+f"(d[0]), "+f"(d[1]), "+f"(d[2]), "+f"(d[3])
        : "r"(a[0]), "r"(a[1]), "r"(a[2]), "r"(a[3]), "r"(b[0]), "r"(b[1]));
}

__global__ __launch_bounds__(512, 1)
void nsa_mma(const float* __restrict__ x,
             const float* __restrict__ Wk,
             const float* __restrict__ bk,
             const float* __restrict__ Wv,
             const float* __restrict__ bv,
             float* __restrict__ out) {
    extern __shared__ float sm[];
    uint32_t* smu = reinterpret_cast<uint32_t*>(sm);

    const int t = threadIdx.x;
    const int half = t >> 8;                    // 0 or 1: which s this thread works
    const int tl = t & 255;                     // thread id within half
    const int lid = t & 31;
    const int qr = lid >> 2;                    // groupID 0..7
    const int qc = lid & 3;                     // threadID-in-group 0..3
    const int sq = (qr >> 1) + 4 * (qr & 1);    // sigma(qr)
    const int ebk = ((tl >> 5)) * 16;           // warp's e-block base (within half)

    // per-half buffer bases
    const int xb  = OFF_X + half * (16 * SX);
    const int vb  = OFF_V + half * (16 * SV);
    const int ivb = OFF_INV + half * 128;

    // ---- one-time: stage Wk/Wv as tf32, row-major stride SW (512 threads) ----
    #pragma unroll
    for (int i = 0; i < 8; i++) {
        const int l = t + 512 * i;          // float4 index over 128x128
        const int r = l >> 5, c = (l & 31) * 4;
        float4 a = reinterpret_cast<const float4*>(Wk)[l];
        uint4 pa = { f2t(a.x), f2t(a.y), f2t(a.z), f2t(a.w) };
        *reinterpret_cast<uint4*>(&smu[OFF_WK + r * SW + c]) = pa;
        float4 b = reinterpret_cast<const float4*>(Wv)[l];
        uint4 pb = { f2t(b.x), f2t(b.y), f2t(b.z), f2t(b.w) };
        *reinterpret_cast<uint4*>(&smu[OFF_WV + r * SW + c]) = pb;
    }
    const float bk0 = __ldg(bk + ebk + qr), bk1 = __ldg(bk + ebk + qr + 8);
    const float bv0 = __ldg(bv + ebk + qr), bv1 = __ldg(bv + ebk + qr + 8);
    const float C2 = 0.015939678942f;       // log2(e)/sqrt(8192)

    const int step = 2 * (int)gridDim.x;
    int s0 = blockIdx.x;                        // half-0's s (loop control)
    int s  = s0 + half * (int)gridDim.x;        // this half's s
    float4 xr0, xr1;
    if (s < S_TOTAL) {
        const float4* xg = reinterpret_cast<const float4*>(x + (size_t)s * 2048);
        xr0 = xg[tl]; xr1 = xg[tl + 256];
    }
    __syncthreads();

    while (s0 < S_TOTAL) {
        // ---- stage x (tf32) into this half's [b][j] stride SX ----
        {
            const int b0i = tl >> 5,         c0 = (tl & 31) * 4;
            const int b1i = (tl + 256) >> 5, c1 = ((tl + 256) & 31) * 4;
            uint4 h;
            h.x = f2t(xr0.x); h.y = f2t(xr0.y); h.z = f2t(xr0.z); h.w = f2t(xr0.w);
            *reinterpret_cast<uint4*>(&smu[xb + b0i * SX + c0]) = h;
            h.x = f2t(xr1.x); h.y = f2t(xr1.y); h.z = f2t(xr1.z); h.w = f2t(xr1.w);
            *reinterpret_cast<uint4*>(&smu[xb + b1i * SX + c1]) = h;
        }
        __syncthreads();                        // (A)

        // ---- prefetch next x into regs ----
        const int snext = s + step;
        if (snext < S_TOTAL) {
            const float4* xg = reinterpret_cast<const float4*>(x + (size_t)snext * 2048);
            xr0 = xg[tl]; xr1 = xg[tl + 256];
        }

        // ======== phase 1: kT = Wk@xT, vT = Wv@xT (M=e16, N=b16 sigma-mapped) ====
        // xf cached for kk 0..7 only (register budget); kk 8..15 use transients.
        uint32_t xf[8][4];
        float kD[2][4] = {{0,0,0,0},{0,0,0,0}};
        float vD[2][4] = {{0,0,0,0},{0,0,0,0}};
        #pragma unroll
        for (int kk = 0; kk < 16; kk++) {
            const int jb = kk * 8;
            uint32_t aK[4], aV[4], xt[4];
            aK[0] = smu[OFF_WK + (ebk + qr) * SW + jb + qc];
            aK[1] = smu[OFF_WK + (ebk + qr + 8) * SW + jb + qc];
            aK[2] = smu[OFF_WK + (ebk + qr) * SW + jb + qc + 4];
            aK[3] = smu[OFF_WK + (ebk + qr + 8) * SW + jb + qc + 4];
            aV[0] = smu[OFF_WV + (ebk + qr) * SW + jb + qc];
            aV[1] = smu[OFF_WV + (ebk + qr + 8) * SW + jb + qc];
            aV[2] = smu[OFF_WV + (ebk + qr) * SW + jb + qc + 4];
            aV[3] = smu[OFF_WV + (ebk + qr + 8) * SW + jb + qc + 4];
            xt[0] = smu[xb + sq * SX + jb + qc];
            xt[1] = smu[xb + sq * SX + jb + qc + 4];
            xt[2] = smu[xb + (sq + 8) * SX + jb + qc];
            xt[3] = smu[xb + (sq + 8) * SX + jb + qc + 4];
            if (kk < 8) {
                xf[kk][0] = xt[0]; xf[kk][1] = xt[1];
                xf[kk][2] = xt[2]; xf[kk][3] = xt[3];
            }
            mma8(kD[0], aK, &xt[0]); mma8(kD[1], aK, &xt[2]);
            mma8(vD[0], aV, &xt[0]); mma8(vD[1], aV, &xt[2]);
        }

        // k: straight into P2 A-fragments (registers; sigma makes layouts match)
        uint32_t ka0[4], ka1[4];
        ka0[0] = f2t(kD[0][0] + bk0); ka0[1] = f2t(kD[0][2] + bk1);
        ka0[2] = f2t(kD[0][1] + bk0); ka0[3] = f2t(kD[0][3] + bk1);
        ka1[0] = f2t(kD[1][0] + bk0); ka1[1] = f2t(kD[1][2] + bk1);
        ka1[2] = f2t(kD[1][1] + bk0); ka1[3] = f2t(kD[1][3] + bk1);

        // v -> smem [b][f], b-cols sigma-mapped
        #pragma unroll
        for (int nt = 0; nt < 2; nt++) {
            const int b0c = nt * 8 + qc;
            smu[vb + b0c * SV + ebk + qr]           = f2t(vD[nt][0] + bv0);
            smu[vb + (b0c + 4) * SV + ebk + qr]     = f2t(vD[nt][1] + bv0);
            smu[vb + b0c * SV + ebk + qr + 8]       = f2t(vD[nt][2] + bv1);
            smu[vb + (b0c + 4) * SV + ebk + qr + 8] = f2t(vD[nt][3] + bv1);
        }
        __syncthreads();                        // (B)

        // ======== fused phase 2+3 per f-tile: scores->exp->O accumulate ========
        float Oe[2][4] = {{0,0,0,0},{0,0,0,0}};
        float Oo[2][4] = {{0,0,0,0},{0,0,0,0}};
        float s0sum = 0.0f, s1sum = 0.0f;
        #pragma unroll
        for (int nt = 0; nt < 16; nt++) {
            float S4[4] = {0, 0, 0, 0};
            uint32_t b[2];
            b[0] = smu[vb + qc * SV + nt * 8 + sq];
            b[1] = smu[vb + (qc + 4) * SV + nt * 8 + sq];
            mma8(S4, ka0, b);
            b[0] = smu[vb + (8 + qc) * SV + nt * 8 + sq];
            b[1] = smu[vb + (8 + qc + 4) * SV + nt * 8 + sq];
            mma8(S4, ka1, b);
            const float e0 = ex2f(S4[0] * C2), e1 = ex2f(S4[1] * C2);
            const float e2 = ex2f(S4[2] * C2), e3 = ex2f(S4[3] * C2);
            s0sum += e0 + e1;
            s1sum += e2 + e3;
            uint32_t bf0[2] = { f2t(e0), f2t(e1) };
            uint32_t bf1[2] = { f2t(e2), f2t(e3) };
            uint32_t a[4];
            if (nt < 8) {
                a[0] = xf[nt][0]; a[1] = xf[nt][2]; a[2] = xf[nt][1]; a[3] = xf[nt][3];
            } else {
                const int fb = nt * 8;
                a[0] = smu[xb + sq * SX + fb + qc];
                a[1] = smu[xb + (sq + 8) * SX + fb + qc];
                a[2] = smu[xb + sq * SX + fb + qc + 4];
                a[3] = smu[xb + (sq + 8) * SX + fb + qc + 4];
            }
            float* O0 = (nt & 1) ? Oo[0] : Oe[0];
            float* O1 = (nt & 1) ? Oo[1] : Oe[1];
            mma8(O0, a, bf0);
            mma8(O1, a, bf1);
        }

        // row sums (e = ebk+qr / +8) -> inv
        s0sum += __shfl_xor_sync(0xffffffffu, s0sum, 1);
        s0sum += __shfl_xor_sync(0xffffffffu, s0sum, 2);
        s1sum += __shfl_xor_sync(0xffffffffu, s1sum, 1);
        s1sum += __shfl_xor_sync(0xffffffffu, s1sum, 2);
        if (qc == 0) {
            sm[ivb + ebk + qr]     = 1.0f / s0sum;
            sm[ivb + ebk + qr + 8] = 1.0f / s1sum;
        }
        __syncthreads();                        // (C)

        // ======== epilogue: out[b=sigma(qr)(+8)][e] = O * inv[e] ========
        if (s < S_TOTAL) {
            float* op = out + (size_t)s * 2048;
            #pragma unroll
            for (int nt2 = 0; nt2 < 2; nt2++) {
                const int ec = ebk + nt2 * 8 + 2 * qc;
                const float ia = sm[ivb + ec];
                const float ib = sm[ivb + ec + 1];
                const float o0 = Oe[nt2][0] + Oo[nt2][0];
                const float o1 = Oe[nt2][1] + Oo[nt2][1];
                const float o2 = Oe[nt2][2] + Oo[nt2][2];
                const float o3 = Oe[nt2][3] + Oo[nt2][3];
                *reinterpret_cast<float2*>(&op[sq * 128 + ec]) =
                    make_float2(o0 * ia, o1 * ib);
                *reinterpret_cast<float2*>(&op[(sq + 8) * 128 + ec]) =
                    make_float2(o2 * ia, o3 * ib);
            }
        }
        s0 += step; s += step;
    }
}

extern "C" void kernel_launch(void* const* d_in, const int* in_sizes, int n_in,
                              void* d_out, int out_size) {
    const float* x  = (const float*)d_in[0];
    const float* Wk = (const float*)d_in[1];
    const float* bk = (const float*)d_in[2];
    const float* Wv = (const float*)d_in[3];
    const float* bv = (const float*)d_in[4];
    float* out = (float*)d_out;

    int sms = 148;
    cudaDeviceGetAttribute(&sms, cudaDevAttrMultiProcessorCount, 0);
    if (sms <= 0) sms = 148;
    cudaFuncSetAttribute(nsa_mma, cudaFuncAttributeMaxDynamicSharedMemorySize, SMEM_BYTES);
    nsa_mma<<<sms, 512, SMEM_BYTES>>>(x, Wk, bk, Wv, bv, out);
}

// round 15
// speedup vs baseline: 1.7207x; 1.0838x over previous
#include <cuda_runtime.h>
#include <cstdint>

// NativeSparseAttention: S=8192, B=16, E=128, fp32
// Persistent kernel, warp-level tf32 mma.sync (m16n8k8).
// R14 = R13 + per-half named barriers (halves decouple; they share only the
// read-only W tile) + raw-fp32 tf32 operands for E/k fragments (HW truncates
// low mantissa bits; drops ~72 cvt/thread/iter off the ALU pipe).

#define S_TOTAL 8192

// strides (floats)
#define SW 132    // W: bank 4*qr+qc          -> conflict-free
#define SX 132    // x: bank 4*sigma(qr)+qc   -> conflict-free
#define SV 136    // v: bank 8*qc+sigma(qr)   -> conflict-free

// smem offsets (floats)
#define OFF_WK  0
#define OFF_WV  (128 * SW)                 // 16896
#define OFF_X   (OFF_WV + 128 * SW)        // 33792 ; 2 halves x 16 x SX
#define OFF_V   (OFF_X + 2 * 16 * SX)      // 38016 ; 2 halves x 16 x SV
#define OFF_INV (OFF_V + 2 * 16 * SV)      // 42368 ; 2 halves x 128
#define SMEM_FLOATS (OFF_INV + 256)        // 42624
#define SMEM_BYTES  (SMEM_FLOATS * 4)      // 170496

__device__ __forceinline__ uint32_t f2t(float f) {
    uint32_t u; asm("cvt.rna.tf32.f32 %0, %1;" : "=r"(u) : "f"(f)); return u;
}
__device__ __forceinline__ float ex2f(float x) {
    float y; asm("ex2.approx.f32 %0, %1;" : "=f"(y) : "f"(x)); return y;
}
__device__ __forceinline__ void mma8(float* d, const uint32_t* a, const uint32_t* b) {
    asm volatile(
        "mma.sync.aligned.m16n8k8.row.col.f32.tf32.tf32.f32 "
        "{%0,%1,%2,%3}, {%4,%5,%6,%7}, {%8,%9}, {%0,%1,%2,%3};"
        : "+f"(d[0]), "+f"(d[1]), "+f"(d[2]), "+f"(d[3])
        : "r"(a[0]), "r"(a[1]), "r"(a[2]), "r"(a[3]), "r"(b[0]), "r"(b[1]));
}

__global__ __launch_bounds__(512, 1)
void nsa_mma(const float* __restrict__ x,
             const float* __restrict__ Wk,
             const float* __restrict__ bk,
             const float* __restrict__ Wv,
             const float* __restrict__ bv,
             float* __restrict__ out) {
    extern __shared__ float sm[];
    uint32_t* smu = reinterpret_cast<uint32_t*>(sm);

    const int t = threadIdx.x;
    const int half = t >> 8;                    // 0 or 1: which s this thread works
    const int tl = t & 255;                     // thread id within half
    const int lid = t & 31;
    const int qr = lid >> 2;                    // groupID 0..7
    const int qc = lid & 3;                     // threadID-in-group 0..3
    const int sq = (qr >> 1) + 4 * (qr & 1);    // sigma(qr)
    const int ebk = ((tl >> 5)) * 16;           // warp's e-block base (within half)
    const int barid = 1 + half;                 // per-half named barrier

    // per-half buffer bases
    const int xb  = OFF_X + half * (16 * SX);
    const int vb  = OFF_V + half * (16 * SV);
    const int ivb = OFF_INV + half * 128;

    // ---- one-time: stage Wk/Wv as tf32, row-major stride SW (512 threads) ----
    #pragma unroll
    for (int i = 0; i < 8; i++) {
        const int l = t + 512 * i;          // float4 index over 128x128
        const int r = l >> 5, c = (l & 31) * 4;
        float4 a = reinterpret_cast<const float4*>(Wk)[l];
        uint4 pa = { f2t(a.x), f2t(a.y), f2t(a.z), f2t(a.w) };
        *reinterpret_cast<uint4*>(&smu[OFF_WK + r * SW + c]) = pa;
        float4 b = reinterpret_cast<const float4*>(Wv)[l];
        uint4 pb = { f2t(b.x), f2t(b.y), f2t(b.z), f2t(b.w) };
        *reinterpret_cast<uint4*>(&smu[OFF_WV + r * SW + c]) = pb;
    }
    const float bk0 = __ldg(bk + ebk + qr), bk1 = __ldg(bk + ebk + qr + 8);
    const float bv0 = __ldg(bv + ebk + qr), bv1 = __ldg(bv + ebk + qr + 8);
    const float C2 = 0.015939678942f;       // log2(e)/sqrt(8192)

    const int step = 2 * (int)gridDim.x;
    int s0 = blockIdx.x;                        // half-0's s (loop control)
    int s  = s0 + half * (int)gridDim.x;        // this half's s
    float4 xr0, xr1;
    if (s < S_TOTAL) {
        const float4* xg = reinterpret_cast<const float4*>(x + (size_t)s * 2048);
        xr0 = xg[tl]; xr1 = xg[tl + 256];
    }
    __syncthreads();   // W visible to all; last full-CTA barrier

    while (s0 < S_TOTAL) {
        // ---- stage x (tf32) into this half's [b][j] stride SX ----
        {
            const int b0i = tl >> 5,         c0 = (tl & 31) * 4;
            const int b1i = (tl + 256) >> 5, c1 = ((tl + 256) & 31) * 4;
            uint4 h;
            h.x = f2t(xr0.x); h.y = f2t(xr0.y); h.z = f2t(xr0.z); h.w = f2t(xr0.w);
            *reinterpret_cast<uint4*>(&smu[xb + b0i * SX + c0]) = h;
            h.x = f2t(xr1.x); h.y = f2t(xr1.y); h.z = f2t(xr1.z); h.w = f2t(xr1.w);
            *reinterpret_cast<uint4*>(&smu[xb + b1i * SX + c1]) = h;
        }
        asm volatile("bar.sync %0, 256;" :: "r"(barid) : "memory");   // (A)

        // ---- prefetch next x into regs ----
        const int snext = s + step;
        if (snext < S_TOTAL) {
            const float4* xg = reinterpret_cast<const float4*>(x + (size_t)snext * 2048);
            xr0 = xg[tl]; xr1 = xg[tl + 256];
        }

        // ======== phase 1: kT = Wk@xT, vT = Wv@xT (M=e16, N=b16 sigma-mapped) ====
        // xf cached for kk 0..7 only (register budget); kk 8..15 use transients.
        uint32_t xf[8][4];
        float kD[2][4] = {{0,0,0,0},{0,0,0,0}};
        float vD[2][4] = {{0,0,0,0},{0,0,0,0}};
        #pragma unroll
        for (int kk = 0; kk < 16; kk++) {
            const int jb = kk * 8;
            uint32_t aK[4], aV[4], xt[4];
            aK[0] = smu[OFF_WK + (ebk + qr) * SW + jb + qc];
            aK[1] = smu[OFF_WK + (ebk + qr + 8) * SW + jb + qc];
            aK[2] = smu[OFF_WK + (ebk + qr) * SW + jb + qc + 4];
            aK[3] = smu[OFF_WK + (ebk + qr + 8) * SW + jb + qc + 4];
            aV[0] = smu[OFF_WV + (ebk + qr) * SW + jb + qc];
            aV[1] = smu[OFF_WV + (ebk + qr + 8) * SW + jb + qc];
            aV[2] = smu[OFF_WV + (ebk + qr) * SW + jb + qc + 4];
            aV[3] = smu[OFF_WV + (ebk + qr + 8) * SW + jb + qc + 4];
            xt[0] = smu[xb + sq * SX + jb + qc];
            xt[1] = smu[xb + sq * SX + jb + qc + 4];
            xt[2] = smu[xb + (sq + 8) * SX + jb + qc];
            xt[3] = smu[xb + (sq + 8) * SX + jb + qc + 4];
            if (kk < 8) {
                xf[kk][0] = xt[0]; xf[kk][1] = xt[1];
                xf[kk][2] = xt[2]; xf[kk][3] = xt[3];
            }
            mma8(kD[0], aK, &xt[0]); mma8(kD[1], aK, &xt[2]);
            mma8(vD[0], aV, &xt[0]); mma8(vD[1], aV, &xt[2]);
        }

        // k: straight into P2 A-fragments (raw fp32 bits; HW truncates to tf32)
        uint32_t ka0[4], ka1[4];
        ka0[0] = __float_as_uint(kD[0][0] + bk0); ka0[1] = __float_as_uint(kD[0][2] + bk1);
        ka0[2] = __float_as_uint(kD[0][1] + bk0); ka0[3] = __float_as_uint(kD[0][3] + bk1);
        ka1[0] = __float_as_uint(kD[1][0] + bk0); ka1[1] = __float_as_uint(kD[1][2] + bk1);
        ka1[2] = __float_as_uint(kD[1][1] + bk0); ka1[3] = __float_as_uint(kD[1][3] + bk1);

        // v -> smem [b][f], b-cols sigma-mapped (keep RN conversion: one-time)
        #pragma unroll
        for (int nt = 0; nt < 2; nt++) {
            const int b0c = nt * 8 + qc;
            smu[vb + b0c * SV + ebk + qr]           = f2t(vD[nt][0] + bv0);
            smu[vb + (b0c + 4) * SV + ebk + qr]     = f2t(vD[nt][1] + bv0);
            smu[vb + b0c * SV + ebk + qr + 8]       = f2t(vD[nt][2] + bv1);
            smu[vb + (b0c + 4) * SV + ebk + qr + 8] = f2t(vD[nt][3] + bv1);
        }
        asm volatile("bar.sync %0, 256;" :: "r"(barid) : "memory");   // (B)

        // ======== fused phase 2+3 per f-tile: scores->exp->O accumulate ========
        float Oe[2][4] = {{0,0,0,0},{0,0,0,0}};
        float Oo[2][4] = {{0,0,0,0},{0,0,0,0}};
        float s0sum = 0.0f, s1sum = 0.0f;
        #pragma unroll
        for (int nt = 0; nt < 16; nt++) {
            float S4[4] = {0, 0, 0, 0};
            uint32_t b[2];
            b[0] = smu[vb + qc * SV + nt * 8 + sq];
            b[1] = smu[vb + (qc + 4) * SV + nt * 8 + sq];
            mma8(S4, ka0, b);
            b[0] = smu[vb + (8 + qc) * SV + nt * 8 + sq];
            b[1] = smu[vb + (8 + qc + 4) * SV + nt * 8 + sq];
            mma8(S4, ka1, b);
            const float e0 = ex2f(S4[0] * C2), e1 = ex2f(S4[1] * C2);
            const float e2 = ex2f(S4[2] * C2), e3 = ex2f(S4[3] * C2);
            s0sum += e0 + e1;
            s1sum += e2 + e3;
            // raw fp32 bits as tf32 operands (HW truncation)
            uint32_t bf0[2] = { __float_as_uint(e0), __float_as_uint(e1) };
            uint32_t bf1[2] = { __float_as_uint(e2), __float_as_uint(e3) };
            uint32_t a[4];
            if (nt < 8) {
                a[0] = xf[nt][0]; a[1] = xf[nt][2]; a[2] = xf[nt][1]; a[3] = xf[nt][3];
            } else {
                const int fb = nt * 8;
                a[0] = smu[xb + sq * SX + fb + qc];
                a[1] = smu[xb + (sq + 8) * SX + fb + qc];
                a[2] = smu[xb + sq * SX + fb + qc + 4];
                a[3] = smu[xb + (sq + 8) * SX + fb + qc + 4];
            }
            float* O0 = (nt & 1) ? Oo[0] : Oe[0];
            float* O1 = (nt & 1) ? Oo[1] : Oe[1];
            mma8(O0, a, bf0);
            mma8(O1, a, bf1);
        }

        // row sums (e = ebk+qr / +8) -> inv
        s0sum += __shfl_xor_sync(0xffffffffu, s0sum, 1);
        s0sum += __shfl_xor_sync(0xffffffffu, s0sum, 2);
        s1sum += __shfl_xor_sync(0xffffffffu, s1sum, 1);
        s1sum += __shfl_xor_sync(0xffffffffu, s1sum, 2);
        if (qc == 0) {
            sm[ivb + ebk + qr]     = 1.0f / s0sum;
            sm[ivb + ebk + qr + 8] = 1.0f / s1sum;
        }
        asm volatile("bar.sync %0, 256;" :: "r"(barid) : "memory");   // (C)

        // ======== epilogue: out[b=sigma(qr)(+8)][e] = O * inv[e] ========
        if (s < S_TOTAL) {
            float* op = out + (size_t)s * 2048;
            #pragma unroll
            for (int nt2 = 0; nt2 < 2; nt2++) {
                const int ec = ebk + nt2 * 8 + 2 * qc;
                const float ia = sm[ivb + ec];
                const float ib = sm[ivb + ec + 1];
                const float o0 = Oe[nt2][0] + Oo[nt2][0];
                const float o1 = Oe[nt2][1] + Oo[nt2][1];
                const float o2 = Oe[nt2][2] + Oo[nt2][2];
                const float o3 = Oe[nt2][3] + Oo[nt2][3];
                *reinterpret_cast<float2*>(&op[sq * 128 + ec]) =
                    make_float2(o0 * ia, o1 * ib);
                *reinterpret_cast<float2*>(&op[(sq + 8) * 128 + ec]) =
                    make_float2(o2 * ia, o3 * ib);
            }
        }
        s0 += step; s += step;
    }
}

extern "C" void kernel_launch(void* const* d_in, const int* in_sizes, int n_in,
                              void* d_out, int out_size) {
    const float* x  = (const float*)d_in[0];
    const float* Wk = (const float*)d_in[1];
    const float* bk = (const float*)d_in[2];
    const float* Wv = (const float*)d_in[3];
    const float* bv = (const float*)d_in[4];
    float* out = (float*)d_out;

    int sms = 148;
    cudaDeviceGetAttribute(&sms, cudaDevAttrMultiProcessorCount, 0);
    if (sms <= 0) sms = 148;
    cudaFuncSetAttribute(nsa_mma, cudaFuncAttributeMaxDynamicSharedMemorySize, SMEM_BYTES);
    nsa_mma<<<sms, 512, SMEM_BYTES>>>(x, Wk, bk, Wv, bv, out);
}